// round 14
// baseline (speedup 1.0000x reference)
#include <cuda_runtime.h>
#include <cuda_fp16.h>
#include <math.h>
#include <stdint.h>

// Problem dims (fixed by reference)
#define Bdim 4
#define Sdim 2048
#define Edim 1024
#define Hdim 16
#define DKdim 64
#define FFNdim 4096
#define NQdim 8
#define NTOK (Bdim * Sdim)
#define EPSv 1e-5f
#define EXPC 0.18033688011112042f    // 0.125 * log2(e)
#define CSHIFT 7.2134752044448169f   // 5.0 * log2(e) -> p = exp(s/8 - 5), fp16-safe

// Scratch (alloc-free rule: __device__ globals)
__device__ float g_attn[(size_t)NTOK * Edim];        // 33.5 MB
__device__ float g_h[(size_t)NTOK * Edim];           // 33.5 MB
__device__ float g_qout[NTOK * NQdim];               // 256 KB
__device__ __half g_w2f[(size_t)Edim * FFNdim];      // 8.4 MB (fp16)
__device__ __half g_xf[(size_t)NTOK * Edim];         // 16.8 MB (fp16 Q/K)
__device__ __half g_xT[(size_t)NTOK * Edim];         // 16.8 MB (V^T, fp16)

// ---------------------------------------------------------------------------
// Helpers
// ---------------------------------------------------------------------------
__device__ __forceinline__ uint32_t smem_u32(const void* p) {
    uint32_t a;
    asm("{ .reg .u64 t; cvta.to.shared.u64 t, %1; cvt.u32.u64 %0, t; }"
        : "=r"(a) : "l"(p));
    return a;
}
__device__ __forceinline__ uint32_t cvt_tf32_u(float v) {
    uint32_t t;
    asm("cvt.rna.tf32.f32 %0, %1;" : "=r"(t) : "f"(v));
    return t;
}
// pack two f32 -> f16x2: lo half = 'lo', hi half = 'hi'
__device__ __forceinline__ uint32_t pack_f16(float lo, float hi) {
    uint32_t d;
    asm("cvt.rn.f16x2.f32 %0, %1, %2;" : "=r"(d) : "f"(hi), "f"(lo));
    return d;
}
__device__ __forceinline__ float ex2f(float x) {
    float r;
    asm("ex2.approx.f32 %0, %1;" : "=f"(r) : "f"(x));
    return r;
}
__device__ __forceinline__ void mma_tf32(float c[4], const uint32_t a[4],
                                         const uint32_t b[2]) {
    asm volatile(
        "mma.sync.aligned.m16n8k8.row.col.f32.tf32.tf32.f32 "
        "{%0,%1,%2,%3}, {%4,%5,%6,%7}, {%8,%9}, {%0,%1,%2,%3};"
        : "+f"(c[0]), "+f"(c[1]), "+f"(c[2]), "+f"(c[3])
        : "r"(a[0]), "r"(a[1]), "r"(a[2]), "r"(a[3]), "r"(b[0]), "r"(b[1]));
}
__device__ __forceinline__ void mma_f16(float c[4], const uint32_t a[4],
                                        const uint32_t b[2]) {
    asm volatile(
        "mma.sync.aligned.m16n8k16.row.col.f32.f16.f16.f32 "
        "{%0,%1,%2,%3}, {%4,%5,%6,%7}, {%8,%9}, {%0,%1,%2,%3};"
        : "+f"(c[0]), "+f"(c[1]), "+f"(c[2]), "+f"(c[3])
        : "r"(a[0]), "r"(a[1]), "r"(a[2]), "r"(a[3]), "r"(b[0]), "r"(b[1]));
}
__device__ __forceinline__ void ldm_x4(uint32_t r[4], uint32_t a) {
    asm volatile("ldmatrix.sync.aligned.m8n8.x4.shared.b16 {%0,%1,%2,%3}, [%4];"
                 : "=r"(r[0]), "=r"(r[1]), "=r"(r[2]), "=r"(r[3]) : "r"(a));
}
__device__ __forceinline__ void cp16(uint32_t dst, const void* src) {
    asm volatile("cp.async.ca.shared.global [%0], [%1], 16;" :: "r"(dst), "l"(src));
}
__device__ __forceinline__ void cp_commit() {
    asm volatile("cp.async.commit_group;" ::: "memory");
}
template <int N>
__device__ __forceinline__ void cp_wait() {
    asm volatile("cp.async.wait_group %0;" :: "n"(N) : "memory");
}

// ---------------------------------------------------------------------------
// Fused prep: per (b,h,s-tile) emit BOTH the row-major fp16 copy (xf) and the
// transposed V^T fp16 tensor (xT) from one read of x.
// ---------------------------------------------------------------------------
__global__ void __launch_bounds__(256) prep_kernel(const float* __restrict__ x,
                                                   __half* __restrict__ xf,
                                                   __half* __restrict__ xT) {
    __shared__ float t[64][65];
    const int bh = blockIdx.y, b = bh >> 4, h = bh & 15;
    const int s0 = blockIdx.x << 6;
    const int tid = threadIdx.x;
#pragma unroll
    for (int i = 0; i < 4; i++) {
        int idx = tid + i * 256;
        int r = idx >> 4, c4 = idx & 15;
        size_t g = ((size_t)(b * Sdim + s0 + r)) * Edim + h * DKdim + c4 * 4;
        float4 v = *(const float4*)(x + g);
        t[r][c4 * 4 + 0] = v.x;
        t[r][c4 * 4 + 1] = v.y;
        t[r][c4 * 4 + 2] = v.z;
        t[r][c4 * 4 + 3] = v.w;
        uint2 o;
        o.x = pack_f16(v.x, v.y);
        o.y = pack_f16(v.z, v.w);
        *(uint2*)(xf + g) = o;
    }
    __syncthreads();
    uint32_t* out = (uint32_t*)(xT + ((size_t)bh * DKdim) * Sdim + s0);
#pragma unroll
    for (int i = 0; i < 8; i++) {
        int idx = tid + i * 256;
        int d = idx >> 5, k2 = idx & 31;
        out[(size_t)d * (Sdim / 2) + k2] = pack_f16(t[2 * k2][d], t[2 * k2 + 1][d]);
    }
}

// ---------------------------------------------------------------------------
// w2 -> fp16 copy
// ---------------------------------------------------------------------------
__global__ void __launch_bounds__(256) cvt_w2_kernel(const float* __restrict__ w2,
                                                     __half* __restrict__ w2f) {
    size_t i = ((size_t)blockIdx.x * 256 + threadIdx.x) * 4;
    float4 v = *(const float4*)(w2 + i);
    uint2 o;
    o.x = pack_f16(v.x, v.y);
    o.y = pack_f16(v.z, v.w);
    *(uint2*)(w2f + i) = o;
}

// ---------------------------------------------------------------------------
// Attention (unchanged from R12): all-fp16 single-pass, hoisted Q fragments.
// Block: one (b,h), 128-query tile, 256 threads = 8 warps, warp tile 16x64.
// ---------------------------------------------------------------------------
#define KSTR 36
#define QT 128
#define KT 64
#define NKT (Sdim / KT)
#define OFF_K  (QT * KSTR)                 // 4608
#define OFF_V  (OFF_K + 2 * KT * KSTR)     // 9216
#define ATTN_WORDS (OFF_V + 2 * KT * KSTR) // 13824
#define ATTN_SMEM (ATTN_WORDS * 4)         // 55296 B

__global__ void __launch_bounds__(256) attn_kernel(const __half* __restrict__ xf,
                                                   const __half* __restrict__ xT,
                                                   float* __restrict__ attn) {
    extern __shared__ uint32_t su[];
    const uint32_t sb = smem_u32(su);

    const int bh = blockIdx.y, b = bh >> 4, h = bh & 15;
    const int q0 = blockIdx.x << 7;
    const int tid = threadIdx.x, lane = tid & 31, w = tid >> 5;
    const int R = w * 16;
    const int r0 = lane >> 2, c0 = lane & 3;

    const uint32_t laneA =
        (uint32_t)((R + (lane & 7) + 8 * ((lane >> 3) & 1)) * KSTR +
                   4 * ((lane >> 4) & 1));
    const uint32_t laneB =
        (uint32_t)(((lane & 7) + 8 * ((lane >> 4) & 1)) * KSTR +
                   4 * ((lane >> 3) & 1));

    const size_t xrow = (size_t)b * Sdim * Edim + h * DKdim;
    const __half* qf = xf + xrow;
    const __half* vt = xT + (size_t)bh * DKdim * Sdim;

    // ---- load Q tile (fp16) ----
#pragma unroll
    for (int i = 0; i < 4; i++) {
        int idx = tid + i * 256;
        int r = idx >> 3, ch = idx & 7;
        cp16(sb + (uint32_t)((r * KSTR + ch * 4) * 4),
             qf + (size_t)(q0 + r) * Edim + ch * 8);
    }
    cp_commit();

    auto load_kv = [&](int bf, int kt) {
#pragma unroll
        for (int i = 0; i < 2; i++) {
            int idx = tid + i * 256;
            int r = idx >> 3, ch = idx & 7;
            uint32_t off = OFF_K + bf * KT * KSTR + r * KSTR + ch * 4;
            cp16(sb + off * 4, qf + (size_t)(kt * KT + r) * Edim + ch * 8);
        }
#pragma unroll
        for (int i = 0; i < 2; i++) {
            int idx = tid + i * 256;
            int d = idx >> 3, ch = idx & 7;
            uint32_t off = OFF_V + bf * KT * KSTR + d * KSTR + ch * 4;
            cp16(sb + off * 4, vt + (size_t)d * Sdim + kt * KT + ch * 8);
        }
        cp_commit();
    };
    load_kv(0, 0);

    cp_wait<0>();
    __syncthreads();
    uint32_t qfr[4][4];
    {
        const uint32_t qa = sb + 4 * laneA;
#pragma unroll
        for (int ks = 0; ks < 4; ks++) ldm_x4(qfr[ks], qa + (uint32_t)(ks * 32));
    }

    float o[8][4] = {};
    float lsum0 = 0.0f, lsum1 = 0.0f;

#pragma unroll 1
    for (int kt = 0; kt < NKT; kt++) {
        const int bf = kt & 1;
        if (kt + 1 < NKT) {
            load_kv(bf ^ 1, kt + 1);
            cp_wait<1>();
        } else {
            cp_wait<0>();
        }
        __syncthreads();

        const uint32_t k_a = sb + 4 * (OFF_K + bf * KT * KSTR + laneB);
        const uint32_t v_a = sb + 4 * (OFF_V + bf * KT * KSTR + laneB);

        float s[8][4] = {};
#pragma unroll
        for (int ks = 0; ks < 4; ks++) {
            const uint32_t kb = (uint32_t)(ks * 32);
#pragma unroll
            for (int ntp = 0; ntp < 4; ntp++) {
                uint32_t k4[4];
                ldm_x4(k4, k_a + (uint32_t)(ntp * 16 * KSTR) * 4 + kb);
                mma_f16(s[2 * ntp], qfr[ks], k4);
                mma_f16(s[2 * ntp + 1], qfr[ks], k4 + 2);
            }
        }

#pragma unroll
        for (int j = 0; j < 4; j++) {
            float p[8];
#pragma unroll
            for (int e = 0; e < 4; e++)
                p[e] = ex2f(fmaf(s[2 * j][e], EXPC, -CSHIFT));
#pragma unroll
            for (int e = 0; e < 4; e++)
                p[4 + e] = ex2f(fmaf(s[2 * j + 1][e], EXPC, -CSHIFT));
            lsum0 += p[0] + p[1] + p[4] + p[5];
            lsum1 += p[2] + p[3] + p[6] + p[7];
            uint32_t ap[4];
            ap[0] = pack_f16(p[0], p[1]);
            ap[1] = pack_f16(p[2], p[3]);
            ap[2] = pack_f16(p[4], p[5]);
            ap[3] = pack_f16(p[6], p[7]);

            const uint32_t kb = (uint32_t)(j * 32);
#pragma unroll
            for (int ntp = 0; ntp < 4; ntp++) {
                uint32_t bv4[4];
                ldm_x4(bv4, v_a + (uint32_t)(ntp * 16 * KSTR) * 4 + kb);
                mma_f16(o[2 * ntp], ap, bv4);
                mma_f16(o[2 * ntp + 1], ap, bv4 + 2);
            }
        }
        __syncthreads();
    }

    lsum0 += __shfl_xor_sync(0xffffffffu, lsum0, 1);
    lsum0 += __shfl_xor_sync(0xffffffffu, lsum0, 2);
    lsum1 += __shfl_xor_sync(0xffffffffu, lsum1, 1);
    lsum1 += __shfl_xor_sync(0xffffffffu, lsum1, 2);
    const float li0 = 1.0f / lsum0, li1 = 1.0f / lsum1;

    float* ob = attn + ((size_t)b * Sdim + q0 + R) * Edim + h * DKdim;
#pragma unroll
    for (int nt = 0; nt < 8; nt++) {
        const int cc = nt * 8 + c0 * 2;
        float2 v0, v1;
        v0.x = o[nt][0] * li0; v0.y = o[nt][1] * li0;
        v1.x = o[nt][2] * li1; v1.y = o[nt][3] * li1;
        *(float2*)(ob + (size_t)r0 * Edim + cc) = v0;
        *(float2*)(ob + (size_t)(r0 + 8) * Edim + cc) = v1;
    }
}

// ---------------------------------------------------------------------------
// Residual + LayerNorm, float4-vectorized. One block per token, 256 threads,
// each owns 4 contiguous elements.
// ---------------------------------------------------------------------------
__global__ void __launch_bounds__(256) ln_kernel(const float* __restrict__ a,
                                                 const float* __restrict__ resid,
                                                 const float* __restrict__ gamma,
                                                 const float* __restrict__ beta,
                                                 float* __restrict__ out,
                                                 float* __restrict__ qout,
                                                 const float* __restrict__ theta) {
    const int t = blockIdx.x;
    const int tid = threadIdx.x;
    const int e = tid * 4;
    const float* pa = a + (size_t)t * Edim;

    float4 v = *(const float4*)(pa + e);
    if (resid) {
        float4 rv = *(const float4*)(resid + (size_t)t * Edim + e);
        v.x += rv.x; v.y += rv.y; v.z += rv.z; v.w += rv.w;
    }
    float s = v.x + v.y + v.z + v.w;
    float s2 = v.x * v.x + v.y * v.y + v.z * v.z + v.w * v.w;
#pragma unroll
    for (int off = 16; off > 0; off >>= 1) {
        s  += __shfl_down_sync(0xffffffffu, s, off);
        s2 += __shfl_down_sync(0xffffffffu, s2, off);
    }
    __shared__ float r1[8], r2[8], stat[2];
    const int warp = tid >> 5, lane = tid & 31;
    if (lane == 0) { r1[warp] = s; r2[warp] = s2; }
    __syncthreads();
    if (tid == 0) {
        float S1 = 0.0f, S2 = 0.0f;
#pragma unroll
        for (int wi = 0; wi < 8; wi++) { S1 += r1[wi]; S2 += r2[wi]; }
        float mu = S1 * (1.0f / Edim);
        float var = S2 * (1.0f / Edim) - mu * mu;
        stat[0] = mu;
        stat[1] = rsqrtf(var + EPSv);
    }
    __syncthreads();
    const float mu = stat[0], rs = stat[1];

    float4 g = *(const float4*)(gamma + e);
    float4 bt = *(const float4*)(beta + e);
    float4 ov;
    ov.x = (v.x - mu) * rs * g.x + bt.x;
    ov.y = (v.y - mu) * rs * g.y + bt.y;
    ov.z = (v.z - mu) * rs * g.z + bt.z;
    ov.w = (v.w - mu) * rs * g.w + bt.w;
    *(float4*)(out + (size_t)t * Edim + e) = ov;

    if (qout != nullptr && tid < 2) {
        float hv[4] = {ov.x, ov.y, ov.z, ov.w};
#pragma unroll
        for (int k = 0; k < 4; k++)
            qout[t * NQdim + e + k] = cosf(hv[k]) * cosf(theta[e + k]);
    }
}

// ---------------------------------------------------------------------------
// Fused FFN, 512 threads, 16 warps, warp tile 16t x 64e (CTA 128x128):
// out = h + relu(qout @ w1^T + b1) @ w2f^T + b2
// ---------------------------------------------------------------------------
#define FSTR 36
#define FK 64
#define NFCH (FFNdim / FK)            // 64
#define FOFF_A 0
#define FOFF_B (QT * FSTR)
#define FOFF_W1 (FOFF_B + 2 * QT * FSTR)
#define FOFF_B1 (FOFF_W1 + 2 * FK * 8)
#define FFN_WORDS (FOFF_B1 + 2 * FK)
#define FFN_SMEM (FFN_WORDS * 4)          // 59904 B

__global__ void __launch_bounds__(512, 2) ffn_fused(const float* __restrict__ qout,
                                                    const float* __restrict__ w1,
                                                    const float* __restrict__ b1,
                                                    const __half* __restrict__ w2f,
                                                    const float* __restrict__ b2,
                                                    const float* __restrict__ hres,
                                                    float* __restrict__ out) {
    extern __shared__ uint32_t su[];
    const uint32_t sb = smem_u32(su);
    uint32_t* As32 = su + FOFF_A;
    float* w1s = (float*)(su + FOFF_W1);
    float* b1s = (float*)(su + FOFF_B1);

    const int tid = threadIdx.x, lane = tid & 31, w = tid >> 5;
    const int mw = w >> 1, nw = w & 1;
    const int RM = mw * 16, CN = nw * 64;
    const int r0 = lane >> 2, c0 = lane & 3;
    const int e0 = blockIdx.x * 128;
    const int t0 = blockIdx.y * 128;

    const uint32_t laneA =
        (uint32_t)(((lane & 7) + 8 * ((lane >> 3) & 1)) * FSTR + 4 * ((lane >> 4) & 1));
    const uint32_t laneB =
        (uint32_t)(((lane & 7) + 8 * ((lane >> 4) & 1)) * FSTR + 4 * ((lane >> 3) & 1));

    // qout A-fragment (tf32, m16k8), constant across chunks
    uint32_t aq[4];
#pragma unroll
    for (int j = 0; j < 4; j++) {
        int row = t0 + RM + r0 + (j & 1) * 8;
        int col = c0 + (j >> 1) * 4;
        aq[j] = cvt_tf32_u(qout[row * NQdim + col]);
    }

    auto load_chunk = [&](int ls, int lc) {
        uint32_t Bb = sb + (uint32_t)(FOFF_B + ls * QT * FSTR) * 4;
#pragma unroll
        for (int i = 0; i < 2; i++) {        // B: 128 rows x 8 chunks of 16B
            int idx = tid + i * 512;
            int r = idx >> 3, ch = idx & 7;
            cp16(Bb + (uint32_t)(r * FSTR * 4 + ch * 16),
                 w2f + (size_t)(e0 + r) * FFNdim + lc * FK + ch * 8);
        }
        if (tid < 128) {                     // w1 chunk: 64 rows x 8 floats
            int r = tid >> 1, ch = tid & 1;
            cp16(sb + (uint32_t)(FOFF_W1 + ls * FK * 8 + r * 8 + ch * 4) * 4,
                 w1 + (size_t)(lc * FK + r) * NQdim + ch * 4);
        } else if (tid < 144) {              // b1 chunk: 64 floats
            int i = tid - 128;
            cp16(sb + (uint32_t)(FOFF_B1 + ls * FK + i * 4) * 4, b1 + lc * FK + i * 4);
        }
        cp_commit();
    };
    load_chunk(0, 0);

    float o[8][4] = {};

#pragma unroll 1
    for (int kc = 0; kc < NFCH; kc++) {
        const int s = kc & 1;
        if (kc + 1 < NFCH) {
            load_chunk(s ^ 1, kc + 1);
            cp_wait<1>();
        } else {
            cp_wait<0>();
        }
        __syncthreads();

        // ---- build A tile rows RM..RM+15, cols nw*32..+32, packed fp16 ----
        {
            const float* w1c = w1s + s * FK * 8;
            const float* b1c = b1s + s * FK;
#pragma unroll
            for (int nt2 = 0; nt2 < 4; nt2++) {
                const int f0 = nw * 32 + nt2 * 8;
                uint32_t bw[2];
                bw[0] = cvt_tf32_u(w1c[(f0 + r0) * 8 + c0]);
                bw[1] = cvt_tf32_u(w1c[(f0 + r0) * 8 + c0 + 4]);
                float bv0 = b1c[f0 + c0 * 2], bv1 = b1c[f0 + c0 * 2 + 1];
                float c4[4] = {0.f, 0.f, 0.f, 0.f};
                mma_tf32(c4, aq, bw);
                int row = RM + r0;
                int cw = f0 / 2 + c0;
                As32[row * FSTR + cw] =
                    pack_f16(fmaxf(c4[0] + bv0, 0.0f), fmaxf(c4[1] + bv1, 0.0f));
                As32[(row + 8) * FSTR + cw] =
                    pack_f16(fmaxf(c4[2] + bv0, 0.0f), fmaxf(c4[3] + bv1, 0.0f));
            }
        }
        __syncthreads();

        // ---- GEMM2 chunk (fp16, k16): o += A(16xFK) @ B^T(64xFK) ----
        const uint32_t a_base = sb + 4 * ((uint32_t)(FOFF_A + RM * FSTR) + laneA);
        const uint32_t b_base =
            sb + 4 * ((uint32_t)(FOFF_B + s * QT * FSTR + CN * FSTR) + laneB);
#pragma unroll
        for (int ks = 0; ks < 4; ks++) {
            const uint32_t kb = (uint32_t)(ks * 8) * 4;
            uint32_t a0[4];
            ldm_x4(a0, a_base + kb);
#pragma unroll
            for (int ntp = 0; ntp < 4; ntp++) {
                uint32_t b4[4];
                ldm_x4(b4, b_base + (uint32_t)(ntp * 16 * FSTR) * 4 + kb);
                mma_f16(o[2 * ntp], a0, b4);
                mma_f16(o[2 * ntp + 1], a0, b4 + 2);
            }
        }
        __syncthreads();
    }

    // Epilogue: + b2 + residual h
#pragma unroll
    for (int hh = 0; hh < 2; hh++) {
        int tt = t0 + RM + r0 + hh * 8;
#pragma unroll
        for (int nt = 0; nt < 8; nt++) {
            int ee = e0 + CN + nt * 8 + c0 * 2;
            float2 hv = *(const float2*)(hres + (size_t)tt * Edim + ee);
            float2 bv = *(const float2*)(b2 + ee);
            float2 ov;
            ov.x = o[nt][hh * 2] + hv.x + bv.x;
            ov.y = o[nt][hh * 2 + 1] + hv.y + bv.y;
            *(float2*)(out + (size_t)tt * Edim + ee) = ov;
        }
    }
}

// ---------------------------------------------------------------------------
extern "C" void kernel_launch(void* const* d_in, const int* in_sizes, int n_in,
                              void* d_out, int out_size) {
    const float* x      = (const float*)d_in[0];
    const float* theta  = (const float*)d_in[1];
    const float* w1     = (const float*)d_in[2];
    const float* b1     = (const float*)d_in[3];
    const float* w2     = (const float*)d_in[4];
    const float* b2     = (const float*)d_in[5];
    const float* gamma1 = (const float*)d_in[6];
    const float* beta1  = (const float*)d_in[7];
    const float* gamma2 = (const float*)d_in[8];
    const float* beta2  = (const float*)d_in[9];
    float* out = (float*)d_out;

    float *attn_p, *h_p, *qout_p;
    __half *w2f_p, *xf_p, *xT_p;
    cudaGetSymbolAddress((void**)&attn_p, g_attn);
    cudaGetSymbolAddress((void**)&h_p, g_h);
    cudaGetSymbolAddress((void**)&qout_p, g_qout);
    cudaGetSymbolAddress((void**)&w2f_p, g_w2f);
    cudaGetSymbolAddress((void**)&xf_p, g_xf);
    cudaGetSymbolAddress((void**)&xT_p, g_xT);

    cudaFuncSetAttribute(attn_kernel, cudaFuncAttributeMaxDynamicSharedMemorySize,
                         ATTN_SMEM);
    cudaFuncSetAttribute(ffn_fused, cudaFuncAttributeMaxDynamicSharedMemorySize,
                         FFN_SMEM);

    // 0) precision prep (fused xf + xT; w2 fp16)
    cvt_w2_kernel<<<(Edim * FFNdim) / 1024, 256>>>(w2, w2f_p);
    prep_kernel<<<dim3(Sdim / 64, Bdim * Hdim), 256>>>(x, xf_p, xT_p);
    // 1) attention (all-fp16 mma, hoisted Q frags) -> g_attn
    attn_kernel<<<dim3(Sdim / QT, Bdim * Hdim), 256, ATTN_SMEM>>>(xf_p, xT_p, attn_p);
    // 2) h = LN(x + attn), qout = cos(h[:, :8]) * cos(theta)
    ln_kernel<<<NTOK, 256>>>(x, attn_p, gamma1, beta1, h_p, qout_p, theta);
    // 3) d_out = h + relu(qout @ w1^T + b1) @ w2f^T + b2  (fp16, 512 threads)
    ffn_fused<<<dim3(Edim / 128, NTOK / 128), 512, FFN_SMEM>>>(qout_p, w1, b1, w2f_p,
                                                               b2, h_p, out);
    // 4) d_out = LN(d_out), in place
    ln_kernel<<<NTOK, 256>>>(out, nullptr, gamma2, beta2, out, nullptr, nullptr);
}

// round 15
// speedup vs baseline: 1.1103x; 1.1103x over previous
#include <cuda_runtime.h>
#include <cuda_fp16.h>
#include <math.h>
#include <stdint.h>

// Problem dims (fixed by reference)
#define Bdim 4
#define Sdim 2048
#define Edim 1024
#define Hdim 16
#define DKdim 64
#define FFNdim 4096
#define NQdim 8
#define NTOK (Bdim * Sdim)
#define EPSv 1e-5f
#define EXPC 0.18033688011112042f    // 0.125 * log2(e)
#define CSHIFT 7.2134752044448169f   // 5.0 * log2(e) -> p = exp(s/8 - 5), fp16-safe

// Scratch (alloc-free rule: __device__ globals)
__device__ float g_attn[(size_t)NTOK * Edim];        // 33.5 MB
__device__ float g_h[(size_t)NTOK * Edim];           // 33.5 MB
__device__ float g_qout[NTOK * NQdim];               // 256 KB
__device__ __half g_w2f[(size_t)Edim * FFNdim];      // 8.4 MB (fp16)
__device__ __half g_xf[(size_t)NTOK * Edim];         // 16.8 MB (fp16 Q/K)
__device__ __half g_xT[(size_t)NTOK * Edim];         // 16.8 MB (V^T, fp16)

// ---------------------------------------------------------------------------
// Helpers
// ---------------------------------------------------------------------------
__device__ __forceinline__ uint32_t smem_u32(const void* p) {
    uint32_t a;
    asm("{ .reg .u64 t; cvta.to.shared.u64 t, %1; cvt.u32.u64 %0, t; }"
        : "=r"(a) : "l"(p));
    return a;
}
__device__ __forceinline__ uint32_t cvt_tf32_u(float v) {
    uint32_t t;
    asm("cvt.rna.tf32.f32 %0, %1;" : "=r"(t) : "f"(v));
    return t;
}
// pack two f32 -> f16x2: lo half = 'lo', hi half = 'hi'
__device__ __forceinline__ uint32_t pack_f16(float lo, float hi) {
    uint32_t d;
    asm("cvt.rn.f16x2.f32 %0, %1, %2;" : "=r"(d) : "f"(hi), "f"(lo));
    return d;
}
__device__ __forceinline__ float ex2f(float x) {
    float r;
    asm("ex2.approx.f32 %0, %1;" : "=f"(r) : "f"(x));
    return r;
}
__device__ __forceinline__ void mma_tf32(float c[4], const uint32_t a[4],
                                         const uint32_t b[2]) {
    asm volatile(
        "mma.sync.aligned.m16n8k8.row.col.f32.tf32.tf32.f32 "
        "{%0,%1,%2,%3}, {%4,%5,%6,%7}, {%8,%9}, {%0,%1,%2,%3};"
        : "+f"(c[0]), "+f"(c[1]), "+f"(c[2]), "+f"(c[3])
        : "r"(a[0]), "r"(a[1]), "r"(a[2]), "r"(a[3]), "r"(b[0]), "r"(b[1]));
}
__device__ __forceinline__ void mma_f16(float c[4], const uint32_t a[4],
                                        const uint32_t b[2]) {
    asm volatile(
        "mma.sync.aligned.m16n8k16.row.col.f32.f16.f16.f32 "
        "{%0,%1,%2,%3}, {%4,%5,%6,%7}, {%8,%9}, {%0,%1,%2,%3};"
        : "+f"(c[0]), "+f"(c[1]), "+f"(c[2]), "+f"(c[3])
        : "r"(a[0]), "r"(a[1]), "r"(a[2]), "r"(a[3]), "r"(b[0]), "r"(b[1]));
}
__device__ __forceinline__ void ldm_x4(uint32_t r[4], uint32_t a) {
    asm volatile("ldmatrix.sync.aligned.m8n8.x4.shared.b16 {%0,%1,%2,%3}, [%4];"
                 : "=r"(r[0]), "=r"(r[1]), "=r"(r[2]), "=r"(r[3]) : "r"(a));
}
__device__ __forceinline__ void cp16(uint32_t dst, const void* src) {
    asm volatile("cp.async.ca.shared.global [%0], [%1], 16;" :: "r"(dst), "l"(src));
}
__device__ __forceinline__ void cp_commit() {
    asm volatile("cp.async.commit_group;" ::: "memory");
}
template <int N>
__device__ __forceinline__ void cp_wait() {
    asm volatile("cp.async.wait_group %0;" :: "n"(N) : "memory");
}

// ---------------------------------------------------------------------------
// Fused prep: per (b,h,s-tile) emit BOTH the row-major fp16 copy (xf) and the
// transposed V^T fp16 tensor (xT) from one read of x.
// ---------------------------------------------------------------------------
__global__ void __launch_bounds__(256) prep_kernel(const float* __restrict__ x,
                                                   __half* __restrict__ xf,
                                                   __half* __restrict__ xT) {
    __shared__ float t[64][65];
    const int bh = blockIdx.y, b = bh >> 4, h = bh & 15;
    const int s0 = blockIdx.x << 6;
    const int tid = threadIdx.x;
#pragma unroll
    for (int i = 0; i < 4; i++) {
        int idx = tid + i * 256;
        int r = idx >> 4, c4 = idx & 15;
        size_t g = ((size_t)(b * Sdim + s0 + r)) * Edim + h * DKdim + c4 * 4;
        float4 v = *(const float4*)(x + g);
        t[r][c4 * 4 + 0] = v.x;
        t[r][c4 * 4 + 1] = v.y;
        t[r][c4 * 4 + 2] = v.z;
        t[r][c4 * 4 + 3] = v.w;
        uint2 o;
        o.x = pack_f16(v.x, v.y);
        o.y = pack_f16(v.z, v.w);
        *(uint2*)(xf + g) = o;
    }
    __syncthreads();
    uint32_t* out = (uint32_t*)(xT + ((size_t)bh * DKdim) * Sdim + s0);
#pragma unroll
    for (int i = 0; i < 8; i++) {
        int idx = tid + i * 256;
        int d = idx >> 5, k2 = idx & 31;
        out[(size_t)d * (Sdim / 2) + k2] = pack_f16(t[2 * k2][d], t[2 * k2 + 1][d]);
    }
}

// ---------------------------------------------------------------------------
// w2 -> fp16 copy
// ---------------------------------------------------------------------------
__global__ void __launch_bounds__(256) cvt_w2_kernel(const float* __restrict__ w2,
                                                     __half* __restrict__ w2f) {
    size_t i = ((size_t)blockIdx.x * 256 + threadIdx.x) * 4;
    float4 v = *(const float4*)(w2 + i);
    uint2 o;
    o.x = pack_f16(v.x, v.y);
    o.y = pack_f16(v.z, v.w);
    *(uint2*)(w2f + i) = o;
}

// ---------------------------------------------------------------------------
// Attention (R12, unchanged): all-fp16 single-pass, hoisted Q fragments.
// Block: one (b,h), 128-query tile, 256 threads = 8 warps, warp tile 16x64.
// ---------------------------------------------------------------------------
#define KSTR 36
#define QT 128
#define KT 64
#define NKT (Sdim / KT)
#define OFF_K  (QT * KSTR)                 // 4608
#define OFF_V  (OFF_K + 2 * KT * KSTR)     // 9216
#define ATTN_WORDS (OFF_V + 2 * KT * KSTR) // 13824
#define ATTN_SMEM (ATTN_WORDS * 4)         // 55296 B

__global__ void __launch_bounds__(256) attn_kernel(const __half* __restrict__ xf,
                                                   const __half* __restrict__ xT,
                                                   float* __restrict__ attn) {
    extern __shared__ uint32_t su[];
    const uint32_t sb = smem_u32(su);

    const int bh = blockIdx.y, b = bh >> 4, h = bh & 15;
    const int q0 = blockIdx.x << 7;
    const int tid = threadIdx.x, lane = tid & 31, w = tid >> 5;
    const int R = w * 16;
    const int r0 = lane >> 2, c0 = lane & 3;

    const uint32_t laneA =
        (uint32_t)((R + (lane & 7) + 8 * ((lane >> 3) & 1)) * KSTR +
                   4 * ((lane >> 4) & 1));
    const uint32_t laneB =
        (uint32_t)(((lane & 7) + 8 * ((lane >> 4) & 1)) * KSTR +
                   4 * ((lane >> 3) & 1));

    const size_t xrow = (size_t)b * Sdim * Edim + h * DKdim;
    const __half* qf = xf + xrow;
    const __half* vt = xT + (size_t)bh * DKdim * Sdim;

    // ---- load Q tile (fp16) ----
#pragma unroll
    for (int i = 0; i < 4; i++) {
        int idx = tid + i * 256;
        int r = idx >> 3, ch = idx & 7;
        cp16(sb + (uint32_t)((r * KSTR + ch * 4) * 4),
             qf + (size_t)(q0 + r) * Edim + ch * 8);
    }
    cp_commit();

    auto load_kv = [&](int bf, int kt) {
#pragma unroll
        for (int i = 0; i < 2; i++) {
            int idx = tid + i * 256;
            int r = idx >> 3, ch = idx & 7;
            uint32_t off = OFF_K + bf * KT * KSTR + r * KSTR + ch * 4;
            cp16(sb + off * 4, qf + (size_t)(kt * KT + r) * Edim + ch * 8);
        }
#pragma unroll
        for (int i = 0; i < 2; i++) {
            int idx = tid + i * 256;
            int d = idx >> 3, ch = idx & 7;
            uint32_t off = OFF_V + bf * KT * KSTR + d * KSTR + ch * 4;
            cp16(sb + off * 4, vt + (size_t)d * Sdim + kt * KT + ch * 8);
        }
        cp_commit();
    };
    load_kv(0, 0);

    cp_wait<0>();
    __syncthreads();
    uint32_t qfr[4][4];
    {
        const uint32_t qa = sb + 4 * laneA;
#pragma unroll
        for (int ks = 0; ks < 4; ks++) ldm_x4(qfr[ks], qa + (uint32_t)(ks * 32));
    }

    float o[8][4] = {};
    float lsum0 = 0.0f, lsum1 = 0.0f;

#pragma unroll 1
    for (int kt = 0; kt < NKT; kt++) {
        const int bf = kt & 1;
        if (kt + 1 < NKT) {
            load_kv(bf ^ 1, kt + 1);
            cp_wait<1>();
        } else {
            cp_wait<0>();
        }
        __syncthreads();

        const uint32_t k_a = sb + 4 * (OFF_K + bf * KT * KSTR + laneB);
        const uint32_t v_a = sb + 4 * (OFF_V + bf * KT * KSTR + laneB);

        float s[8][4] = {};
#pragma unroll
        for (int ks = 0; ks < 4; ks++) {
            const uint32_t kb = (uint32_t)(ks * 32);
#pragma unroll
            for (int ntp = 0; ntp < 4; ntp++) {
                uint32_t k4[4];
                ldm_x4(k4, k_a + (uint32_t)(ntp * 16 * KSTR) * 4 + kb);
                mma_f16(s[2 * ntp], qfr[ks], k4);
                mma_f16(s[2 * ntp + 1], qfr[ks], k4 + 2);
            }
        }

#pragma unroll
        for (int j = 0; j < 4; j++) {
            float p[8];
#pragma unroll
            for (int e = 0; e < 4; e++)
                p[e] = ex2f(fmaf(s[2 * j][e], EXPC, -CSHIFT));
#pragma unroll
            for (int e = 0; e < 4; e++)
                p[4 + e] = ex2f(fmaf(s[2 * j + 1][e], EXPC, -CSHIFT));
            lsum0 += p[0] + p[1] + p[4] + p[5];
            lsum1 += p[2] + p[3] + p[6] + p[7];
            uint32_t ap[4];
            ap[0] = pack_f16(p[0], p[1]);
            ap[1] = pack_f16(p[2], p[3]);
            ap[2] = pack_f16(p[4], p[5]);
            ap[3] = pack_f16(p[6], p[7]);

            const uint32_t kb = (uint32_t)(j * 32);
#pragma unroll
            for (int ntp = 0; ntp < 4; ntp++) {
                uint32_t bv4[4];
                ldm_x4(bv4, v_a + (uint32_t)(ntp * 16 * KSTR) * 4 + kb);
                mma_f16(o[2 * ntp], ap, bv4);
                mma_f16(o[2 * ntp + 1], ap, bv4 + 2);
            }
        }
        __syncthreads();
    }

    lsum0 += __shfl_xor_sync(0xffffffffu, lsum0, 1);
    lsum0 += __shfl_xor_sync(0xffffffffu, lsum0, 2);
    lsum1 += __shfl_xor_sync(0xffffffffu, lsum1, 1);
    lsum1 += __shfl_xor_sync(0xffffffffu, lsum1, 2);
    const float li0 = 1.0f / lsum0, li1 = 1.0f / lsum1;

    float* ob = attn + ((size_t)b * Sdim + q0 + R) * Edim + h * DKdim;
#pragma unroll
    for (int nt = 0; nt < 8; nt++) {
        const int cc = nt * 8 + c0 * 2;
        float2 v0, v1;
        v0.x = o[nt][0] * li0; v0.y = o[nt][1] * li0;
        v1.x = o[nt][2] * li1; v1.y = o[nt][3] * li1;
        *(float2*)(ob + (size_t)r0 * Edim + cc) = v0;
        *(float2*)(ob + (size_t)(r0 + 8) * Edim + cc) = v1;
    }
}

// ---------------------------------------------------------------------------
// Residual + LayerNorm, float4-vectorized (R13 version, neutral-positive).
// ---------------------------------------------------------------------------
__global__ void __launch_bounds__(256) ln_kernel(const float* __restrict__ a,
                                                 const float* __restrict__ resid,
                                                 const float* __restrict__ gamma,
                                                 const float* __restrict__ beta,
                                                 float* __restrict__ out,
                                                 float* __restrict__ qout,
                                                 const float* __restrict__ theta) {
    const int t = blockIdx.x;
    const int tid = threadIdx.x;
    const int e = tid * 4;
    const float* pa = a + (size_t)t * Edim;

    float4 v = *(const float4*)(pa + e);
    if (resid) {
        float4 rv = *(const float4*)(resid + (size_t)t * Edim + e);
        v.x += rv.x; v.y += rv.y; v.z += rv.z; v.w += rv.w;
    }
    float s = v.x + v.y + v.z + v.w;
    float s2 = v.x * v.x + v.y * v.y + v.z * v.z + v.w * v.w;
#pragma unroll
    for (int off = 16; off > 0; off >>= 1) {
        s  += __shfl_down_sync(0xffffffffu, s, off);
        s2 += __shfl_down_sync(0xffffffffu, s2, off);
    }
    __shared__ float r1[8], r2[8], stat[2];
    const int warp = tid >> 5, lane = tid & 31;
    if (lane == 0) { r1[warp] = s; r2[warp] = s2; }
    __syncthreads();
    if (tid == 0) {
        float S1 = 0.0f, S2 = 0.0f;
#pragma unroll
        for (int wi = 0; wi < 8; wi++) { S1 += r1[wi]; S2 += r2[wi]; }
        float mu = S1 * (1.0f / Edim);
        float var = S2 * (1.0f / Edim) - mu * mu;
        stat[0] = mu;
        stat[1] = rsqrtf(var + EPSv);
    }
    __syncthreads();
    const float mu = stat[0], rs = stat[1];

    float4 g = *(const float4*)(gamma + e);
    float4 bt = *(const float4*)(beta + e);
    float4 ov;
    ov.x = (v.x - mu) * rs * g.x + bt.x;
    ov.y = (v.y - mu) * rs * g.y + bt.y;
    ov.z = (v.z - mu) * rs * g.z + bt.z;
    ov.w = (v.w - mu) * rs * g.w + bt.w;
    *(float4*)(out + (size_t)t * Edim + e) = ov;

    if (qout != nullptr && tid < 2) {
        float hv[4] = {ov.x, ov.y, ov.z, ov.w};
#pragma unroll
        for (int k = 0; k < 4; k++)
            qout[t * NQdim + e + k] = cosf(hv[k]) * cosf(theta[e + k]);
    }
}

// ---------------------------------------------------------------------------
// Fused FFN (R12 256-thread version, verbatim — the measured-best config):
// out = h + relu(qout @ w1^T + b1) @ w2f^T + b2
// CTA: 128 tokens x 128 e, 256 threads, 8 warps (32x64 tiles), K chunks of 64.
// ---------------------------------------------------------------------------
#define FSTR 36
#define FK 64
#define NFCH (FFNdim / FK)            // 64
#define FOFF_A 0
#define FOFF_B (QT * FSTR)
#define FOFF_W1 (FOFF_B + 2 * QT * FSTR)
#define FOFF_B1 (FOFF_W1 + 2 * FK * 8)
#define FFN_WORDS (FOFF_B1 + 2 * FK)
#define FFN_SMEM (FFN_WORDS * 4)          // 59904 B

__global__ void __launch_bounds__(256) ffn_fused(const float* __restrict__ qout,
                                                 const float* __restrict__ w1,
                                                 const float* __restrict__ b1,
                                                 const __half* __restrict__ w2f,
                                                 const float* __restrict__ b2,
                                                 const float* __restrict__ hres,
                                                 float* __restrict__ out) {
    extern __shared__ uint32_t su[];
    const uint32_t sb = smem_u32(su);
    uint32_t* As32 = su + FOFF_A;
    float* w1s = (float*)(su + FOFF_W1);
    float* b1s = (float*)(su + FOFF_B1);

    const int tid = threadIdx.x, lane = tid & 31, w = tid >> 5;
    const int mw = w >> 1, nw = w & 1;
    const int RM = mw * 32, CN = nw * 64;
    const int r0 = lane >> 2, c0 = lane & 3;
    const int e0 = blockIdx.x * 128;
    const int t0 = blockIdx.y * 128;

    const uint32_t laneA =
        (uint32_t)(((lane & 7) + 8 * ((lane >> 3) & 1)) * FSTR + 4 * ((lane >> 4) & 1));
    const uint32_t laneB =
        (uint32_t)(((lane & 7) + 8 * ((lane >> 4) & 1)) * FSTR + 4 * ((lane >> 3) & 1));

    uint32_t aq[2][4];
#pragma unroll
    for (int mt = 0; mt < 2; mt++) {
#pragma unroll
        for (int j = 0; j < 4; j++) {
            int row = t0 + RM + mt * 16 + r0 + (j & 1) * 8;
            int col = c0 + (j >> 1) * 4;
            aq[mt][j] = cvt_tf32_u(qout[row * NQdim + col]);
        }
    }

    auto load_chunk = [&](int ls, int lc) {
        uint32_t Bb = sb + (uint32_t)(FOFF_B + ls * QT * FSTR) * 4;
#pragma unroll
        for (int i = 0; i < 4; i++) {
            int idx = tid + i * 256;
            int r = idx >> 3, ch = idx & 7;
            cp16(Bb + (uint32_t)(r * FSTR * 4 + ch * 16),
                 w2f + (size_t)(e0 + r) * FFNdim + lc * FK + ch * 8);
        }
        if (tid < 128) {
            int r = tid >> 1, ch = tid & 1;
            cp16(sb + (uint32_t)(FOFF_W1 + ls * FK * 8 + r * 8 + ch * 4) * 4,
                 w1 + (size_t)(lc * FK + r) * NQdim + ch * 4);
        } else if (tid < 144) {
            int i = tid - 128;
            cp16(sb + (uint32_t)(FOFF_B1 + ls * FK + i * 4) * 4, b1 + lc * FK + i * 4);
        }
        cp_commit();
    };
    load_chunk(0, 0);

    float o[2][8][4] = {};

#pragma unroll 1
    for (int kc = 0; kc < NFCH; kc++) {
        const int s = kc & 1;
        if (kc + 1 < NFCH) {
            load_chunk(s ^ 1, kc + 1);
            cp_wait<1>();
        } else {
            cp_wait<0>();
        }
        __syncthreads();

        {
            const float* w1c = w1s + s * FK * 8;
            const float* b1c = b1s + s * FK;
#pragma unroll
            for (int nt2 = 0; nt2 < 4; nt2++) {
                const int f0 = nw * 32 + nt2 * 8;
                uint32_t bw[2];
                bw[0] = cvt_tf32_u(w1c[(f0 + r0) * 8 + c0]);
                bw[1] = cvt_tf32_u(w1c[(f0 + r0) * 8 + c0 + 4]);
                float bv0 = b1c[f0 + c0 * 2], bv1 = b1c[f0 + c0 * 2 + 1];
#pragma unroll
                for (int mt = 0; mt < 2; mt++) {
                    float c4[4] = {0.f, 0.f, 0.f, 0.f};
                    mma_tf32(c4, aq[mt], bw);
                    int row = RM + mt * 16 + r0;
                    int cw = f0 / 2 + c0;
                    As32[row * FSTR + cw] =
                        pack_f16(fmaxf(c4[0] + bv0, 0.0f), fmaxf(c4[1] + bv1, 0.0f));
                    As32[(row + 8) * FSTR + cw] =
                        pack_f16(fmaxf(c4[2] + bv0, 0.0f), fmaxf(c4[3] + bv1, 0.0f));
                }
            }
        }
        __syncthreads();

        const uint32_t a_base = sb + 4 * ((uint32_t)(FOFF_A + RM * FSTR) + laneA);
        const uint32_t b_base =
            sb + 4 * ((uint32_t)(FOFF_B + s * QT * FSTR + CN * FSTR) + laneB);
#pragma unroll
        for (int ks = 0; ks < 4; ks++) {
            const uint32_t kb = (uint32_t)(ks * 8) * 4;
            uint32_t a0[4], a1[4];
            ldm_x4(a0, a_base + kb);
            ldm_x4(a1, a_base + (uint32_t)(16 * FSTR) * 4 + kb);
#pragma unroll
            for (int ntp = 0; ntp < 4; ntp++) {
                uint32_t b4[4];
                ldm_x4(b4, b_base + (uint32_t)(ntp * 16 * FSTR) * 4 + kb);
                mma_f16(o[0][2 * ntp], a0, b4);
                mma_f16(o[1][2 * ntp], a1, b4);
                mma_f16(o[0][2 * ntp + 1], a0, b4 + 2);
                mma_f16(o[1][2 * ntp + 1], a1, b4 + 2);
            }
        }
        __syncthreads();
    }

#pragma unroll
    for (int mt = 0; mt < 2; mt++)
#pragma unroll
        for (int hh = 0; hh < 2; hh++) {
            int tt = t0 + RM + mt * 16 + r0 + hh * 8;
#pragma unroll
            for (int nt = 0; nt < 8; nt++) {
                int ee = e0 + CN + nt * 8 + c0 * 2;
                float2 hv = *(const float2*)(hres + (size_t)tt * Edim + ee);
                float2 bv = *(const float2*)(b2 + ee);
                float2 ov;
                ov.x = o[mt][nt][hh * 2] + hv.x + bv.x;
                ov.y = o[mt][nt][hh * 2 + 1] + hv.y + bv.y;
                *(float2*)(out + (size_t)tt * Edim + ee) = ov;
            }
        }
}

// ---------------------------------------------------------------------------
extern "C" void kernel_launch(void* const* d_in, const int* in_sizes, int n_in,
                              void* d_out, int out_size) {
    const float* x      = (const float*)d_in[0];
    const float* theta  = (const float*)d_in[1];
    const float* w1     = (const float*)d_in[2];
    const float* b1     = (const float*)d_in[3];
    const float* w2     = (const float*)d_in[4];
    const float* b2     = (const float*)d_in[5];
    const float* gamma1 = (const float*)d_in[6];
    const float* beta1  = (const float*)d_in[7];
    const float* gamma2 = (const float*)d_in[8];
    const float* beta2  = (const float*)d_in[9];
    float* out = (float*)d_out;

    float *attn_p, *h_p, *qout_p;
    __half *w2f_p, *xf_p, *xT_p;
    cudaGetSymbolAddress((void**)&attn_p, g_attn);
    cudaGetSymbolAddress((void**)&h_p, g_h);
    cudaGetSymbolAddress((void**)&qout_p, g_qout);
    cudaGetSymbolAddress((void**)&w2f_p, g_w2f);
    cudaGetSymbolAddress((void**)&xf_p, g_xf);
    cudaGetSymbolAddress((void**)&xT_p, g_xT);

    cudaFuncSetAttribute(attn_kernel, cudaFuncAttributeMaxDynamicSharedMemorySize,
                         ATTN_SMEM);
    cudaFuncSetAttribute(ffn_fused, cudaFuncAttributeMaxDynamicSharedMemorySize,
                         FFN_SMEM);

    // 0) precision prep (fused xf + xT; w2 fp16)
    cvt_w2_kernel<<<(Edim * FFNdim) / 1024, 256>>>(w2, w2f_p);
    prep_kernel<<<dim3(Sdim / 64, Bdim * Hdim), 256>>>(x, xf_p, xT_p);
    // 1) attention (all-fp16 mma, hoisted Q frags) -> g_attn
    attn_kernel<<<dim3(Sdim / QT, Bdim * Hdim), 256, ATTN_SMEM>>>(xf_p, xT_p, attn_p);
    // 2) h = LN(x + attn), qout = cos(h[:, :8]) * cos(theta)
    ln_kernel<<<NTOK, 256>>>(x, attn_p, gamma1, beta1, h_p, qout_p, theta);
    // 3) d_out = h + relu(qout @ w1^T + b1) @ w2f^T + b2  (fp16, 256 threads)
    ffn_fused<<<dim3(Edim / 128, NTOK / 128), 256, FFN_SMEM>>>(qout_p, w1, b1, w2f_p,
                                                               b2, h_p, out);
    // 4) d_out = LN(d_out), in place
    ln_kernel<<<NTOK, 256>>>(out, nullptr, gamma2, beta2, out, nullptr, nullptr);
}

// round 16
// speedup vs baseline: 1.1284x; 1.0163x over previous
#include <cuda_runtime.h>
#include <cuda_fp16.h>
#include <math.h>
#include <stdint.h>

// Problem dims (fixed by reference)
#define Bdim 4
#define Sdim 2048
#define Edim 1024
#define Hdim 16
#define DKdim 64
#define FFNdim 4096
#define NQdim 8
#define NTOK (Bdim * Sdim)
#define EPSv 1e-5f
#define EXPC 0.18033688011112042f    // 0.125 * log2(e)
#define CSHIFT 7.2134752044448169f   // 5.0 * log2(e) -> p = exp(s/8 - 5), fp16-safe

// Scratch (alloc-free rule: __device__ globals)
__device__ float g_attn[(size_t)NTOK * Edim];        // 33.5 MB
__device__ float g_h[(size_t)NTOK * Edim];           // 33.5 MB
__device__ float g_qout[NTOK * NQdim];               // 256 KB
__device__ __half g_w2f[(size_t)Edim * FFNdim];      // 8.4 MB (fp16)
__device__ __half g_xf[(size_t)NTOK * Edim];         // 16.8 MB (fp16 Q/K)
__device__ __half g_xT[(size_t)NTOK * Edim];         // 16.8 MB (V^T, fp16)
__device__ __half g_hidf[(size_t)NTOK * FFNdim];     // 67.1 MB (fp16 hid)

// ---------------------------------------------------------------------------
// Helpers
// ---------------------------------------------------------------------------
__device__ __forceinline__ uint32_t smem_u32(const void* p) {
    uint32_t a;
    asm("{ .reg .u64 t; cvta.to.shared.u64 t, %1; cvt.u32.u64 %0, t; }"
        : "=r"(a) : "l"(p));
    return a;
}
// pack two f32 -> f16x2: lo half = 'lo', hi half = 'hi'
__device__ __forceinline__ uint32_t pack_f16(float lo, float hi) {
    uint32_t d;
    asm("cvt.rn.f16x2.f32 %0, %1, %2;" : "=r"(d) : "f"(hi), "f"(lo));
    return d;
}
__device__ __forceinline__ float ex2f(float x) {
    float r;
    asm("ex2.approx.f32 %0, %1;" : "=f"(r) : "f"(x));
    return r;
}
__device__ __forceinline__ void mma_f16(float c[4], const uint32_t a[4],
                                        const uint32_t b[2]) {
    asm volatile(
        "mma.sync.aligned.m16n8k16.row.col.f32.f16.f16.f32 "
        "{%0,%1,%2,%3}, {%4,%5,%6,%7}, {%8,%9}, {%0,%1,%2,%3};"
        : "+f"(c[0]), "+f"(c[1]), "+f"(c[2]), "+f"(c[3])
        : "r"(a[0]), "r"(a[1]), "r"(a[2]), "r"(a[3]), "r"(b[0]), "r"(b[1]));
}
__device__ __forceinline__ void ldm_x4(uint32_t r[4], uint32_t a) {
    asm volatile("ldmatrix.sync.aligned.m8n8.x4.shared.b16 {%0,%1,%2,%3}, [%4];"
                 : "=r"(r[0]), "=r"(r[1]), "=r"(r[2]), "=r"(r[3]) : "r"(a));
}
__device__ __forceinline__ void cp16(uint32_t dst, const void* src) {
    asm volatile("cp.async.ca.shared.global [%0], [%1], 16;" :: "r"(dst), "l"(src));
}
__device__ __forceinline__ void cp_commit() {
    asm volatile("cp.async.commit_group;" ::: "memory");
}
template <int N>
__device__ __forceinline__ void cp_wait() {
    asm volatile("cp.async.wait_group %0;" :: "n"(N) : "memory");
}

// ---------------------------------------------------------------------------
// Fused prep: per (b,h,s-tile) emit BOTH the row-major fp16 copy (xf) and the
// transposed V^T fp16 tensor (xT) from one read of x.
// ---------------------------------------------------------------------------
__global__ void __launch_bounds__(256) prep_kernel(const float* __restrict__ x,
                                                   __half* __restrict__ xf,
                                                   __half* __restrict__ xT) {
    __shared__ float t[64][65];
    const int bh = blockIdx.y, b = bh >> 4, h = bh & 15;
    const int s0 = blockIdx.x << 6;
    const int tid = threadIdx.x;
#pragma unroll
    for (int i = 0; i < 4; i++) {
        int idx = tid + i * 256;
        int r = idx >> 4, c4 = idx & 15;
        size_t g = ((size_t)(b * Sdim + s0 + r)) * Edim + h * DKdim + c4 * 4;
        float4 v = *(const float4*)(x + g);
        t[r][c4 * 4 + 0] = v.x;
        t[r][c4 * 4 + 1] = v.y;
        t[r][c4 * 4 + 2] = v.z;
        t[r][c4 * 4 + 3] = v.w;
        uint2 o;
        o.x = pack_f16(v.x, v.y);
        o.y = pack_f16(v.z, v.w);
        *(uint2*)(xf + g) = o;
    }
    __syncthreads();
    uint32_t* out = (uint32_t*)(xT + ((size_t)bh * DKdim) * Sdim + s0);
#pragma unroll
    for (int i = 0; i < 8; i++) {
        int idx = tid + i * 256;
        int d = idx >> 5, k2 = idx & 31;
        out[(size_t)d * (Sdim / 2) + k2] = pack_f16(t[2 * k2][d], t[2 * k2 + 1][d]);
    }
}

// ---------------------------------------------------------------------------
// w2 -> fp16 copy
// ---------------------------------------------------------------------------
__global__ void __launch_bounds__(256) cvt_w2_kernel(const float* __restrict__ w2,
                                                     __half* __restrict__ w2f) {
    size_t i = ((size_t)blockIdx.x * 256 + threadIdx.x) * 4;
    float4 v = *(const float4*)(w2 + i);
    uint2 o;
    o.x = pack_f16(v.x, v.y);
    o.y = pack_f16(v.z, v.w);
    *(uint2*)(w2f + i) = o;
}

// ---------------------------------------------------------------------------
// hid = relu(qout @ w1^T + b1) -> fp16 [NTOK][FFN]. Each thread owns an
// f-pair (adjacent columns) for a 64-token tile; u32 stores are coalesced.
// ---------------------------------------------------------------------------
__global__ void __launch_bounds__(256) hid_kernel(const float* __restrict__ qout,
                                                  const float* __restrict__ w1,
                                                  const float* __restrict__ b1,
                                                  __half* __restrict__ hidf) {
    __shared__ float qs[64][8];
    const int tid = threadIdx.x;
    const int f = (blockIdx.x * 256 + tid) * 2;
    const int t0 = blockIdx.y * 64;
#pragma unroll
    for (int i = 0; i < 2; i++) {
        int idx = tid + i * 256;
        qs[idx >> 3][idx & 7] = qout[(t0 + (idx >> 3)) * NQdim + (idx & 7)];
    }
    float4 wa0 = *(const float4*)(w1 + (size_t)f * NQdim);
    float4 wb0 = *(const float4*)(w1 + (size_t)f * NQdim + 4);
    float4 wa1 = *(const float4*)(w1 + (size_t)(f + 1) * NQdim);
    float4 wb1 = *(const float4*)(w1 + (size_t)(f + 1) * NQdim + 4);
    float bb0 = b1[f], bb1 = b1[f + 1];
    __syncthreads();
#pragma unroll 4
    for (int t = 0; t < 64; t++) {
        float a0 = bb0, a1 = bb1;
        a0 += qs[t][0] * wa0.x + qs[t][1] * wa0.y + qs[t][2] * wa0.z + qs[t][3] * wa0.w;
        a0 += qs[t][4] * wb0.x + qs[t][5] * wb0.y + qs[t][6] * wb0.z + qs[t][7] * wb0.w;
        a1 += qs[t][0] * wa1.x + qs[t][1] * wa1.y + qs[t][2] * wa1.z + qs[t][3] * wa1.w;
        a1 += qs[t][4] * wb1.x + qs[t][5] * wb1.y + qs[t][6] * wb1.z + qs[t][7] * wb1.w;
        *(uint32_t*)(hidf + (size_t)(t0 + t) * FFNdim + f) =
            pack_f16(fmaxf(a0, 0.0f), fmaxf(a1, 0.0f));
    }
}

// ---------------------------------------------------------------------------
// Attention (R12, unchanged): all-fp16 single-pass, hoisted Q fragments.
// Block: one (b,h), 128-query tile, 256 threads = 8 warps, warp tile 16x64.
// ---------------------------------------------------------------------------
#define KSTR 36
#define QT 128
#define KT 64
#define NKT (Sdim / KT)
#define OFF_K  (QT * KSTR)                 // 4608
#define OFF_V  (OFF_K + 2 * KT * KSTR)     // 9216
#define ATTN_WORDS (OFF_V + 2 * KT * KSTR) // 13824
#define ATTN_SMEM (ATTN_WORDS * 4)         // 55296 B

__global__ void __launch_bounds__(256) attn_kernel(const __half* __restrict__ xf,
                                                   const __half* __restrict__ xT,
                                                   float* __restrict__ attn) {
    extern __shared__ uint32_t su[];
    const uint32_t sb = smem_u32(su);

    const int bh = blockIdx.y, b = bh >> 4, h = bh & 15;
    const int q0 = blockIdx.x << 7;
    const int tid = threadIdx.x, lane = tid & 31, w = tid >> 5;
    const int R = w * 16;
    const int r0 = lane >> 2, c0 = lane & 3;

    const uint32_t laneA =
        (uint32_t)((R + (lane & 7) + 8 * ((lane >> 3) & 1)) * KSTR +
                   4 * ((lane >> 4) & 1));
    const uint32_t laneB =
        (uint32_t)(((lane & 7) + 8 * ((lane >> 4) & 1)) * KSTR +
                   4 * ((lane >> 3) & 1));

    const size_t xrow = (size_t)b * Sdim * Edim + h * DKdim;
    const __half* qf = xf + xrow;
    const __half* vt = xT + (size_t)bh * DKdim * Sdim;

    // ---- load Q tile (fp16) ----
#pragma unroll
    for (int i = 0; i < 4; i++) {
        int idx = tid + i * 256;
        int r = idx >> 3, ch = idx & 7;
        cp16(sb + (uint32_t)((r * KSTR + ch * 4) * 4),
             qf + (size_t)(q0 + r) * Edim + ch * 8);
    }
    cp_commit();

    auto load_kv = [&](int bf, int kt) {
#pragma unroll
        for (int i = 0; i < 2; i++) {
            int idx = tid + i * 256;
            int r = idx >> 3, ch = idx & 7;
            uint32_t off = OFF_K + bf * KT * KSTR + r * KSTR + ch * 4;
            cp16(sb + off * 4, qf + (size_t)(kt * KT + r) * Edim + ch * 8);
        }
#pragma unroll
        for (int i = 0; i < 2; i++) {
            int idx = tid + i * 256;
            int d = idx >> 3, ch = idx & 7;
            uint32_t off = OFF_V + bf * KT * KSTR + d * KSTR + ch * 4;
            cp16(sb + off * 4, vt + (size_t)d * Sdim + kt * KT + ch * 8);
        }
        cp_commit();
    };
    load_kv(0, 0);

    cp_wait<0>();
    __syncthreads();
    uint32_t qfr[4][4];
    {
        const uint32_t qa = sb + 4 * laneA;
#pragma unroll
        for (int ks = 0; ks < 4; ks++) ldm_x4(qfr[ks], qa + (uint32_t)(ks * 32));
    }

    float o[8][4] = {};
    float lsum0 = 0.0f, lsum1 = 0.0f;

#pragma unroll 1
    for (int kt = 0; kt < NKT; kt++) {
        const int bf = kt & 1;
        if (kt + 1 < NKT) {
            load_kv(bf ^ 1, kt + 1);
            cp_wait<1>();
        } else {
            cp_wait<0>();
        }
        __syncthreads();

        const uint32_t k_a = sb + 4 * (OFF_K + bf * KT * KSTR + laneB);
        const uint32_t v_a = sb + 4 * (OFF_V + bf * KT * KSTR + laneB);

        float s[8][4] = {};
#pragma unroll
        for (int ks = 0; ks < 4; ks++) {
            const uint32_t kb = (uint32_t)(ks * 32);
#pragma unroll
            for (int ntp = 0; ntp < 4; ntp++) {
                uint32_t k4[4];
                ldm_x4(k4, k_a + (uint32_t)(ntp * 16 * KSTR) * 4 + kb);
                mma_f16(s[2 * ntp], qfr[ks], k4);
                mma_f16(s[2 * ntp + 1], qfr[ks], k4 + 2);
            }
        }

#pragma unroll
        for (int j = 0; j < 4; j++) {
            float p[8];
#pragma unroll
            for (int e = 0; e < 4; e++)
                p[e] = ex2f(fmaf(s[2 * j][e], EXPC, -CSHIFT));
#pragma unroll
            for (int e = 0; e < 4; e++)
                p[4 + e] = ex2f(fmaf(s[2 * j + 1][e], EXPC, -CSHIFT));
            lsum0 += p[0] + p[1] + p[4] + p[5];
            lsum1 += p[2] + p[3] + p[6] + p[7];
            uint32_t ap[4];
            ap[0] = pack_f16(p[0], p[1]);
            ap[1] = pack_f16(p[2], p[3]);
            ap[2] = pack_f16(p[4], p[5]);
            ap[3] = pack_f16(p[6], p[7]);

            const uint32_t kb = (uint32_t)(j * 32);
#pragma unroll
            for (int ntp = 0; ntp < 4; ntp++) {
                uint32_t bv4[4];
                ldm_x4(bv4, v_a + (uint32_t)(ntp * 16 * KSTR) * 4 + kb);
                mma_f16(o[2 * ntp], ap, bv4);
                mma_f16(o[2 * ntp + 1], ap, bv4 + 2);
            }
        }
        __syncthreads();
    }

    lsum0 += __shfl_xor_sync(0xffffffffu, lsum0, 1);
    lsum0 += __shfl_xor_sync(0xffffffffu, lsum0, 2);
    lsum1 += __shfl_xor_sync(0xffffffffu, lsum1, 1);
    lsum1 += __shfl_xor_sync(0xffffffffu, lsum1, 2);
    const float li0 = 1.0f / lsum0, li1 = 1.0f / lsum1;

    float* ob = attn + ((size_t)b * Sdim + q0 + R) * Edim + h * DKdim;
#pragma unroll
    for (int nt = 0; nt < 8; nt++) {
        const int cc = nt * 8 + c0 * 2;
        float2 v0, v1;
        v0.x = o[nt][0] * li0; v0.y = o[nt][1] * li0;
        v1.x = o[nt][2] * li1; v1.y = o[nt][3] * li1;
        *(float2*)(ob + (size_t)r0 * Edim + cc) = v0;
        *(float2*)(ob + (size_t)(r0 + 8) * Edim + cc) = v1;
    }
}

// ---------------------------------------------------------------------------
// Residual + LayerNorm, float4-vectorized.
// ---------------------------------------------------------------------------
__global__ void __launch_bounds__(256) ln_kernel(const float* __restrict__ a,
                                                 const float* __restrict__ resid,
                                                 const float* __restrict__ gamma,
                                                 const float* __restrict__ beta,
                                                 float* __restrict__ out,
                                                 float* __restrict__ qout,
                                                 const float* __restrict__ theta) {
    const int t = blockIdx.x;
    const int tid = threadIdx.x;
    const int e = tid * 4;
    const float* pa = a + (size_t)t * Edim;

    float4 v = *(const float4*)(pa + e);
    if (resid) {
        float4 rv = *(const float4*)(resid + (size_t)t * Edim + e);
        v.x += rv.x; v.y += rv.y; v.z += rv.z; v.w += rv.w;
    }
    float s = v.x + v.y + v.z + v.w;
    float s2 = v.x * v.x + v.y * v.y + v.z * v.z + v.w * v.w;
#pragma unroll
    for (int off = 16; off > 0; off >>= 1) {
        s  += __shfl_down_sync(0xffffffffu, s, off);
        s2 += __shfl_down_sync(0xffffffffu, s2, off);
    }
    __shared__ float r1[8], r2[8], stat[2];
    const int warp = tid >> 5, lane = tid & 31;
    if (lane == 0) { r1[warp] = s; r2[warp] = s2; }
    __syncthreads();
    if (tid == 0) {
        float S1 = 0.0f, S2 = 0.0f;
#pragma unroll
        for (int wi = 0; wi < 8; wi++) { S1 += r1[wi]; S2 += r2[wi]; }
        float mu = S1 * (1.0f / Edim);
        float var = S2 * (1.0f / Edim) - mu * mu;
        stat[0] = mu;
        stat[1] = rsqrtf(var + EPSv);
    }
    __syncthreads();
    const float mu = stat[0], rs = stat[1];

    float4 g = *(const float4*)(gamma + e);
    float4 bt = *(const float4*)(beta + e);
    float4 ov;
    ov.x = (v.x - mu) * rs * g.x + bt.x;
    ov.y = (v.y - mu) * rs * g.y + bt.y;
    ov.z = (v.z - mu) * rs * g.z + bt.z;
    ov.w = (v.w - mu) * rs * g.w + bt.w;
    *(float4*)(out + (size_t)t * Edim + e) = ov;

    if (qout != nullptr && tid < 2) {
        float hv[4] = {ov.x, ov.y, ov.z, ov.w};
#pragma unroll
        for (int k = 0; k < 4; k++)
            qout[t * NQdim + e + k] = cosf(hv[k]) * cosf(theta[e + k]);
    }
}

// ---------------------------------------------------------------------------
// FFN GEMM (pure): out = h + hidf @ w2f^T + b2, fp16 tensor cores.
// A (hid) and B (w2) both double-buffered via cp.async. No in-loop A build.
// CTA: 128 tokens x 128 e, 256 threads, 8 warps (32x64 tiles), K chunks of 64.
// ---------------------------------------------------------------------------
#define FSTR 36
#define FK 64
#define NFCH (FFNdim / FK)            // 64
#define FOFF_A 0
#define FOFF_B (2 * QT * FSTR)            // 9216
#define FFN_WORDS (4 * QT * FSTR)         // 18432
#define FFN_SMEM (FFN_WORDS * 4)          // 73728 B

__global__ void __launch_bounds__(256) ffn_gemm(const __half* __restrict__ hidf,
                                                const __half* __restrict__ w2f,
                                                const float* __restrict__ b2,
                                                const float* __restrict__ hres,
                                                float* __restrict__ out) {
    extern __shared__ uint32_t su[];
    const uint32_t sb = smem_u32(su);

    const int tid = threadIdx.x, lane = tid & 31, w = tid >> 5;
    const int mw = w >> 1, nw = w & 1;
    const int RM = mw * 32, CN = nw * 64;
    const int r0 = lane >> 2, c0 = lane & 3;
    const int e0 = blockIdx.x * 128;
    const int t0 = blockIdx.y * 128;

    const uint32_t laneA =
        (uint32_t)(((lane & 7) + 8 * ((lane >> 3) & 1)) * FSTR + 4 * ((lane >> 4) & 1));
    const uint32_t laneB =
        (uint32_t)(((lane & 7) + 8 * ((lane >> 4) & 1)) * FSTR + 4 * ((lane >> 3) & 1));

    auto load_chunk = [&](int ls, int lc) {
        uint32_t Ab = sb + (uint32_t)(FOFF_A + ls * QT * FSTR) * 4;
        uint32_t Bb = sb + (uint32_t)(FOFF_B + ls * QT * FSTR) * 4;
#pragma unroll
        for (int i = 0; i < 4; i++) {
            int idx = tid + i * 256;
            int r = idx >> 3, ch = idx & 7;
            uint32_t off = (uint32_t)(r * FSTR * 4 + ch * 16);
            cp16(Ab + off, hidf + (size_t)(t0 + r) * FFNdim + lc * FK + ch * 8);
            cp16(Bb + off, w2f + (size_t)(e0 + r) * FFNdim + lc * FK + ch * 8);
        }
        cp_commit();
    };
    load_chunk(0, 0);

    float o[2][8][4] = {};

#pragma unroll 1
    for (int kc = 0; kc < NFCH; kc++) {
        const int s = kc & 1;
        if (kc + 1 < NFCH) {
            load_chunk(s ^ 1, kc + 1);
            cp_wait<1>();
        } else {
            cp_wait<0>();
        }
        __syncthreads();

        const uint32_t a_base =
            sb + 4 * ((uint32_t)(FOFF_A + s * QT * FSTR + RM * FSTR) + laneA);
        const uint32_t b_base =
            sb + 4 * ((uint32_t)(FOFF_B + s * QT * FSTR + CN * FSTR) + laneB);
#pragma unroll
        for (int ks = 0; ks < 4; ks++) {
            const uint32_t kb = (uint32_t)(ks * 8) * 4;
            uint32_t a0[4], a1[4];
            ldm_x4(a0, a_base + kb);
            ldm_x4(a1, a_base + (uint32_t)(16 * FSTR) * 4 + kb);
#pragma unroll
            for (int ntp = 0; ntp < 4; ntp++) {
                uint32_t b4[4];
                ldm_x4(b4, b_base + (uint32_t)(ntp * 16 * FSTR) * 4 + kb);
                mma_f16(o[0][2 * ntp], a0, b4);
                mma_f16(o[1][2 * ntp], a1, b4);
                mma_f16(o[0][2 * ntp + 1], a0, b4 + 2);
                mma_f16(o[1][2 * ntp + 1], a1, b4 + 2);
            }
        }
        __syncthreads();
    }

    // Epilogue: + b2 + residual h
#pragma unroll
    for (int mt = 0; mt < 2; mt++)
#pragma unroll
        for (int hh = 0; hh < 2; hh++) {
            int tt = t0 + RM + mt * 16 + r0 + hh * 8;
#pragma unroll
            for (int nt = 0; nt < 8; nt++) {
                int ee = e0 + CN + nt * 8 + c0 * 2;
                float2 hv = *(const float2*)(hres + (size_t)tt * Edim + ee);
                float2 bv = *(const float2*)(b2 + ee);
                float2 ov;
                ov.x = o[mt][nt][hh * 2] + hv.x + bv.x;
                ov.y = o[mt][nt][hh * 2 + 1] + hv.y + bv.y;
                *(float2*)(out + (size_t)tt * Edim + ee) = ov;
            }
        }
}

// ---------------------------------------------------------------------------
extern "C" void kernel_launch(void* const* d_in, const int* in_sizes, int n_in,
                              void* d_out, int out_size) {
    const float* x      = (const float*)d_in[0];
    const float* theta  = (const float*)d_in[1];
    const float* w1     = (const float*)d_in[2];
    const float* b1     = (const float*)d_in[3];
    const float* w2     = (const float*)d_in[4];
    const float* b2     = (const float*)d_in[5];
    const float* gamma1 = (const float*)d_in[6];
    const float* beta1  = (const float*)d_in[7];
    const float* gamma2 = (const float*)d_in[8];
    const float* beta2  = (const float*)d_in[9];
    float* out = (float*)d_out;

    float *attn_p, *h_p, *qout_p;
    __half *w2f_p, *xf_p, *xT_p, *hidf_p;
    cudaGetSymbolAddress((void**)&attn_p, g_attn);
    cudaGetSymbolAddress((void**)&h_p, g_h);
    cudaGetSymbolAddress((void**)&qout_p, g_qout);
    cudaGetSymbolAddress((void**)&w2f_p, g_w2f);
    cudaGetSymbolAddress((void**)&xf_p, g_xf);
    cudaGetSymbolAddress((void**)&xT_p, g_xT);
    cudaGetSymbolAddress((void**)&hidf_p, g_hidf);

    cudaFuncSetAttribute(attn_kernel, cudaFuncAttributeMaxDynamicSharedMemorySize,
                         ATTN_SMEM);
    cudaFuncSetAttribute(ffn_gemm, cudaFuncAttributeMaxDynamicSharedMemorySize,
                         FFN_SMEM);

    // 0) precision prep (fused xf + xT; w2 fp16)
    cvt_w2_kernel<<<(Edim * FFNdim) / 1024, 256>>>(w2, w2f_p);
    prep_kernel<<<dim3(Sdim / 64, Bdim * Hdim), 256>>>(x, xf_p, xT_p);
    // 1) attention (all-fp16 mma, hoisted Q frags) -> g_attn
    attn_kernel<<<dim3(Sdim / QT, Bdim * Hdim), 256, ATTN_SMEM>>>(xf_p, xT_p, attn_p);
    // 2) h = LN(x + attn), qout = cos(h[:, :8]) * cos(theta)
    ln_kernel<<<NTOK, 256>>>(x, attn_p, gamma1, beta1, h_p, qout_p, theta);
    // 3) hid = relu(qout @ w1^T + b1) -> fp16
    hid_kernel<<<dim3(FFNdim / 512, NTOK / 64), 256>>>(qout_p, w1, b1, hidf_p);
    // 4) d_out = h + hidf @ w2f^T + b2  (pure fp16 GEMM)
    ffn_gemm<<<dim3(Edim / 128, NTOK / 128), 256, FFN_SMEM>>>(hidf_p, w2f_p, b2,
                                                              h_p, out);
    // 5) d_out = LN(d_out), in place
    ln_kernel<<<NTOK, 256>>>(out, nullptr, gamma2, beta2, out, nullptr, nullptr);
}